// round 1
// baseline (speedup 1.0000x reference)
#include <cuda_runtime.h>
#include <cstdint>

#define BB 64
#define HH 256
#define WW 256
#define RR 8   // truncation radius: exp(-81/2) ~ 2.6e-18, exact to fp32

// scratch (device bss, no runtime allocation)
__device__ float g_tmp[3][BB][HH][WW];   // after W-pass
__device__ float g_map[3][BB][HH][WW];   // after H-pass (unnormalized)
__device__ float g_max[3 * BB];          // per (map, batch) max

// map m -> input channel: m0=target(ch2,s=1), m1=cost(ch1,s=1), m2=hist(ch3,s=0.5)

__global__ void initMaxK() {
    int t = threadIdx.x;
    if (t < 3 * BB) g_max[t] = 0.0f;
}

// Pass 1: threshold mask, convolve along W. One block = one (b, m, row).
__global__ void convWK(const float* __restrict__ x) {
    const int b = blockIdx.z;
    const int m = blockIdx.y;
    const int p = blockIdx.x;
    const int j = threadIdx.x;

    __shared__ float sm[WW];
    const int ch = (m == 0) ? 2 : (m == 1) ? 1 : 3;
    const float* row = x + (((size_t)b * 4 + ch) * HH + p) * WW;
    sm[j] = (row[j] > 0.0f) ? 1.0f : 0.0f;
    __syncthreads();

    const float i2s = (m == 2) ? 2.0f : 0.5f;   // 1/(2*sigma^2)
    float acc = sm[j];
#pragma unroll
    for (int d = 1; d <= RR; d++) {
        float w = __expf(-(float)(d * d) * i2s);
        float s = 0.0f;
        if (j - d >= 0) s += sm[j - d];
        if (j + d < WW) s += sm[j + d];
        acc = fmaf(w, s, acc);
    }
    g_tmp[m][b][p][j] = acc;
}

// Pass 2: convolve along H + per-(m,b) max reduction. One block = one (b, m, out-row).
__global__ void convHK() {
    const int b = blockIdx.z;
    const int m = blockIdx.y;
    const int i = blockIdx.x;
    const int j = threadIdx.x;

    const float i2s = (m == 2) ? 2.0f : 0.5f;
    float acc = g_tmp[m][b][i][j];
#pragma unroll
    for (int d = 1; d <= RR; d++) {
        float w = __expf(-(float)(d * d) * i2s);
        float s = 0.0f;
        if (i - d >= 0) s += g_tmp[m][b][i - d][j];
        if (i + d < HH) s += g_tmp[m][b][i + d][j];
        acc = fmaf(w, s, acc);
    }
    g_map[m][b][i][j] = acc;

    // block-wide max -> one atomic per block (values are >= 0)
    float v = acc;
#pragma unroll
    for (int off = 16; off; off >>= 1)
        v = fmaxf(v, __shfl_xor_sync(0xFFFFFFFFu, v, off));
    __shared__ float wmax[WW / 32];
    if ((j & 31) == 0) wmax[j >> 5] = v;
    __syncthreads();
    if (j < (WW / 32)) {
        v = wmax[j];
#pragma unroll
        for (int off = (WW / 64); off; off >>= 1)
            v = fmaxf(v, __shfl_xor_sync(0xFFu, v, off));
        if (j == 0)
            atomicMax((int*)&g_max[m * BB + b], __float_as_int(v));
    }
}

// Pass 3: normalize + assemble 5 output channels.
__global__ void finalizeK(const float* __restrict__ x, float* __restrict__ out) {
    const int b = blockIdx.y;
    const int i = blockIdx.x;
    const int j = threadIdx.x;

    float mt = g_max[0 * BB + b]; mt = (mt == 0.0f) ? 1.0f : mt;
    float mc = g_max[1 * BB + b]; mc = (mc == 0.0f) ? 1.0f : mc;
    float mh = g_max[2 * BB + b]; mh = (mh == 0.0f) ? 1.0f : mh;

    const float t = g_map[0][b][i][j] / mt;
    const float c = g_map[1][b][i][j] / mc;
    const float h = g_map[2][b][i][j] / mh;

    const size_t px = (size_t)i * WW + j;
    const size_t inb = (size_t)b * 4 * HH * WW;
    const size_t ob  = (size_t)b * 5 * HH * WW;
    const size_t plane = (size_t)HH * WW;

    out[ob + 0 * plane + px] = x[inb + 0 * plane + px];  // ch0 copy
    out[ob + 1 * plane + px] = t;                         // target
    out[ob + 2 * plane + px] = c;                         // cost
    out[ob + 3 * plane + px] = h;                         // hist
    out[ob + 4 * plane + px] = t * c;                     // mul
}

extern "C" void kernel_launch(void* const* d_in, const int* in_sizes, int n_in,
                              void* d_out, int out_size) {
    const float* x = (const float*)d_in[0];
    float* out = (float*)d_out;

    initMaxK<<<1, 256>>>();

    dim3 gconv(HH, 3, BB);
    convWK<<<gconv, WW>>>(x);
    convHK<<<gconv, WW>>>();

    dim3 gfin(HH, BB);
    finalizeK<<<gfin, WW>>>(x, out);
}

// round 2
// speedup vs baseline: 1.1137x; 1.1137x over previous
#include <cuda_runtime.h>
#include <cstdint>

#define BB 64
#define HH 256
#define WW 256
#define RAD 8                    // exp(-81/2) ~ 2.6e-18: exact truncation in fp32
#define TH 64                    // output rows per tile
#define AROWS (TH + 2 * RAD)     // 80 rows incl. halo
#define ASTR  (WW + 2 * RAD)     // 272: zero-padded columns
#define NT 512
#define NTILES (HH / TH)         // 4
#define SMEM_BYTES ((AROWS * ASTR + AROWS * WW) * (int)sizeof(float))  // 168960

__device__ float g_max[3 * BB];  // per (map, batch) unnormalized max

// map m -> input channel: m0=target(ch2,s=1), m1=cost(ch1,s=1), m2=hist(ch3,s=0.5)
__device__ __forceinline__ int map_ch(int m) { return (m == 0) ? 2 : (m == 1) ? 1 : 3; }

__device__ __forceinline__ void load_weights(int m, float* w) {
    const float i2s = (m == 2) ? 2.0f : 0.5f;   // 1/(2*sigma^2)
#pragma unroll
    for (int d = 0; d <= RAD; d++) w[d] = __expf(-(float)(d * d) * i2s);
}

// Fill padded threshold tile As[80][272], then row-wise 17-tap conv into Bs[80][256].
__device__ __forceinline__ void fill_and_convW(
    const float* __restrict__ x, int b, int ch, int row0,
    const float* w, float* As, float* Bs)
{
    const float* src = x + ((size_t)b * 4 + ch) * HH * WW;
    for (int idx = threadIdx.x; idx < AROWS * ASTR; idx += NT) {
        int r = idx / ASTR;
        int c = idx - r * ASTR;
        int gr = row0 - RAD + r;
        int gc = c - RAD;
        float v = 0.0f;
        if ((unsigned)gr < HH && (unsigned)gc < WW)
            v = (src[(size_t)gr * WW + gc] > 0.0f) ? 1.0f : 0.0f;
        As[idx] = v;
    }
    __syncthreads();

    // W-conv: each task = 1 row x 4 consecutive cols via 5 shifted float4 loads
    for (int idx = threadIdx.x; idx < AROWS * (WW / 4); idx += NT) {
        int r = idx >> 6;        // / 64 groups per row
        int g = idx & 63;
        const float4* ap = (const float4*)(As + r * ASTR + 4 * g);  // padded col 4g = center-8
        float a[20];
        float4 v0 = ap[0], v1 = ap[1], v2 = ap[2], v3 = ap[3], v4 = ap[4];
        a[0]=v0.x; a[1]=v0.y; a[2]=v0.z; a[3]=v0.w;
        a[4]=v1.x; a[5]=v1.y; a[6]=v1.z; a[7]=v1.w;
        a[8]=v2.x; a[9]=v2.y; a[10]=v2.z; a[11]=v2.w;
        a[12]=v3.x; a[13]=v3.y; a[14]=v3.z; a[15]=v3.w;
        a[16]=v4.x; a[17]=v4.y; a[18]=v4.z; a[19]=v4.w;
        float o[4];
#pragma unroll
        for (int k = 0; k < 4; k++) {
            float acc = w[0] * a[k + RAD];
#pragma unroll
            for (int d = 1; d <= RAD; d++)
                acc = fmaf(w[d], a[k + RAD - d] + a[k + RAD + d], acc);
            o[k] = acc;
        }
        *(float4*)(Bs + r * WW + 4 * g) = make_float4(o[0], o[1], o[2], o[3]);
    }
    __syncthreads();
}

__global__ void initMaxK() {
    if (threadIdx.x < 3 * BB) g_max[threadIdx.x] = 0.0f;
}

// Kernel 1: compute per-(map,batch) max over the full plane. One block = (tile, b).
__global__ void __launch_bounds__(NT, 1) maxK(const float* __restrict__ x) {
    extern __shared__ float smem[];
    float* As = smem;
    float* Bs = smem + AROWS * ASTR;
    __shared__ float red[16];

    const int row0 = blockIdx.x * TH;
    const int b = blockIdx.y;
    const int j  = threadIdx.x & (WW - 1);
    const int rh = threadIdx.x >> 8;          // 0/1: which half of the tile rows
    const int r0 = rh * (TH / 2);

    for (int m = 0; m < 3; m++) {
        float w[RAD + 1];
        load_weights(m, w);
        fill_and_convW(x, b, map_ch(m), row0, w, As, Bs);

        // H-conv: rolling 17-register window down column j
        float win[17];
#pragma unroll
        for (int k = 0; k < 17; k++) win[k] = Bs[(r0 + k) * WW + j];
        float mx = 0.0f;
#pragma unroll
        for (int t = 0; t < TH / 2; t++) {
            float acc = w[0] * win[RAD];
#pragma unroll
            for (int d = 1; d <= RAD; d++)
                acc = fmaf(w[d], win[RAD - d] + win[RAD + d], acc);
            mx = fmaxf(mx, acc);
#pragma unroll
            for (int k = 0; k < 16; k++) win[k] = win[k + 1];
            if (t < TH / 2 - 1) win[16] = Bs[(r0 + t + 17) * WW + j];
        }

        // block max -> one atomic (values >= 0, int compare is order-preserving)
#pragma unroll
        for (int off = 16; off; off >>= 1)
            mx = fmaxf(mx, __shfl_xor_sync(0xFFFFFFFFu, mx, off));
        if ((threadIdx.x & 31) == 0) red[threadIdx.x >> 5] = mx;
        __syncthreads();
        if (threadIdx.x < 16) {
            float v = red[threadIdx.x];
#pragma unroll
            for (int off = 8; off; off >>= 1)
                v = fmaxf(v, __shfl_xor_sync(0xFFFFu, v, off));
            if (threadIdx.x == 0)
                atomicMax((int*)&g_max[m * BB + b], __float_as_int(v));
        }
        __syncthreads();
    }
}

// Kernel 2: recompute maps, normalize, assemble all 5 channels. One block = (tile, b).
__global__ void __launch_bounds__(NT, 1) outK(const float* __restrict__ x,
                                              float* __restrict__ out) {
    extern __shared__ float smem[];
    float* As = smem;
    float* Bs = smem + AROWS * ASTR;

    const int row0 = blockIdx.x * TH;
    const int b = blockIdx.y;
    const int j  = threadIdx.x & (WW - 1);
    const int rh = threadIdx.x >> 8;
    const int r0 = rh * (TH / 2);

    const size_t plane = (size_t)HH * WW;
    const size_t ib = (size_t)b * 4 * plane;
    const size_t ob = (size_t)b * 5 * plane;

    // ch0 passthrough
#pragma unroll
    for (int t = 0; t < TH / 2; t++) {
        size_t px = (size_t)(row0 + r0 + t) * WW + j;
        out[ob + px] = x[ib + px];
    }

    float inv[3];
#pragma unroll
    for (int m = 0; m < 3; m++) {
        float mx = g_max[m * BB + b];
        inv[m] = (mx == 0.0f) ? 1.0f : 1.0f / mx;
    }

    float stash[TH / 2];   // normalized target values of this thread's pixels

    for (int m = 0; m < 3; m++) {
        float w[RAD + 1];
        load_weights(m, w);
        fill_and_convW(x, b, map_ch(m), row0, w, As, Bs);

        float win[17];
#pragma unroll
        for (int k = 0; k < 17; k++) win[k] = Bs[(r0 + k) * WW + j];
#pragma unroll
        for (int t = 0; t < TH / 2; t++) {
            float acc = w[0] * win[RAD];
#pragma unroll
            for (int d = 1; d <= RAD; d++)
                acc = fmaf(w[d], win[RAD - d] + win[RAD + d], acc);
            acc *= inv[m];
            size_t px = (size_t)(row0 + r0 + t) * WW + j;
            if (m == 0) {
                stash[t] = acc;
                out[ob + 1 * plane + px] = acc;                 // target
            } else if (m == 1) {
                out[ob + 2 * plane + px] = acc;                 // cost
                out[ob + 4 * plane + px] = acc * stash[t];      // mul
            } else {
                out[ob + 3 * plane + px] = acc;                 // hist
            }
#pragma unroll
            for (int k = 0; k < 16; k++) win[k] = win[k + 1];
            if (t < TH / 2 - 1) win[16] = Bs[(r0 + t + 17) * WW + j];
        }
        __syncthreads();   // all Bs reads done before next map's convW rewrites it
    }
}

extern "C" void kernel_launch(void* const* d_in, const int* in_sizes, int n_in,
                              void* d_out, int out_size) {
    const float* x = (const float*)d_in[0];
    float* out = (float*)d_out;

    cudaFuncSetAttribute(maxK, cudaFuncAttributeMaxDynamicSharedMemorySize, SMEM_BYTES);
    cudaFuncSetAttribute(outK, cudaFuncAttributeMaxDynamicSharedMemorySize, SMEM_BYTES);

    initMaxK<<<1, 256>>>();
    dim3 g(NTILES, BB);
    maxK<<<g, NT, SMEM_BYTES>>>(x);
    outK<<<g, NT, SMEM_BYTES>>>(x, out);
}

// round 3
// speedup vs baseline: 2.7231x; 2.4452x over previous
#include <cuda_runtime.h>
#include <cstdint>

#define BB 64
#define HH 256
#define WW 256
#define RAD 6                    // exp(-49/2)~2.3e-11 truncation: invisible at 1e-3 tol
#define NTAP (2 * RAD + 1)       // 13
#define TH 64                    // output rows per block tile
#define AROWS (TH + 2 * RAD)     // 76 rows incl halo
#define AWORDS 68                // padded mask row: 272 bytes = 68 words (8B pad each side)
#define NT 512
#define SMEM_BYTES (AROWS * AWORDS * 4 + AROWS * WW * 4)   // 20672 + 77824 = 98496

__device__ __align__(16) float g_map[3][BB][HH][WW];  // unnormalized maps
__device__ float g_max[3 * BB];                       // zero-init; idempotent across replays

// map m -> input channel: m0=target(ch2,s=1), m1=cost(ch1,s=1), m2=hist(ch3,s=0.5)
__device__ __forceinline__ int map_ch(int m) { return (m == 0) ? 2 : (m == 1) ? 1 : 3; }

// Threshold one channel tile into packed bytes As[76][272B] (8B zero pad each side).
__device__ __forceinline__ void fillA(const float* __restrict__ x, int b, int m,
                                      int row0, uint32_t* As) {
    const float* src = x + ((size_t)b * 4 + map_ch(m)) * (size_t)(HH * WW);
    for (int idx = threadIdx.x; idx < AROWS * 64; idx += NT) {
        int r = idx >> 6, c4 = idx & 63;
        int gr = row0 - RAD + r;
        uint32_t wv = 0;
        if ((unsigned)gr < HH) {
            float4 v = *(const float4*)(src + (size_t)gr * WW + 4 * c4);
            wv = (v.x > 0.f ? 1u : 0u) | (v.y > 0.f ? 0x100u : 0u) |
                 (v.z > 0.f ? 0x10000u : 0u) | (v.w > 0.f ? 0x1000000u : 0u);
        }
        As[r * AWORDS + 2 + c4] = wv;
    }
    for (int idx = threadIdx.x; idx < AROWS * 4; idx += NT) {
        int r = idx >> 2, hw = idx & 3;
        As[r * AWORDS + (hw < 2 ? hw : 64 + hw)] = 0;   // halo words
    }
}

// Row-wise 13-tap conv on packed mask -> Bs[76][256]. 4 outputs per task.
__device__ __forceinline__ void convW(const uint32_t* As, float* Bs, const float* w) {
    for (int idx = threadIdx.x; idx < AROWS * 64; idx += NT) {
        int r = idx >> 6, g = idx & 63;
        const uint32_t* ap = As + r * AWORDS + g;   // byte 4g of padded row
        uint32_t wd[5];
#pragma unroll
        for (int q = 0; q < 5; q++) wd[q] = ap[q];
        // padded col of byte i is 4g+i; output k (out col 4g+k) centers at i=k+8
        float f[18];
#pragma unroll
        for (int i = 2; i < 18; i++)
            f[i] = __uint_as_float(((wd[i >> 2] >> ((i & 3) * 8)) & 0xFFu) * 0x3F800000u);
        float4 o;
        float* op = (float*)&o;
#pragma unroll
        for (int k = 0; k < 4; k++) {
            float acc = w[0] * f[k + 8];
#pragma unroll
            for (int d = 1; d <= RAD; d++)
                acc = fmaf(w[d], f[k + 8 - d] + f[k + 8 + d], acc);
            op[k] = acc;
        }
        *(float4*)(Bs + r * WW + 4 * g) = o;
    }
}

// Column 13-tap conv with rolling register window; stores map, returns thread max.
__device__ __forceinline__ float hconvStore(const float* Bs, const float* w,
                                            float* __restrict__ gdst,
                                            int row0, int j, int rh) {
    const int t0 = rh * (TH / 2);
    float win[NTAP];
#pragma unroll
    for (int k = 0; k < NTAP; k++) win[k] = Bs[(t0 + k) * WW + j];
    float mx = 0.f;
#pragma unroll
    for (int t = 0; t < TH / 2; t++) {
        float acc = w[0] * win[RAD];
#pragma unroll
        for (int d = 1; d <= RAD; d++)
            acc = fmaf(w[d], win[RAD - d] + win[RAD + d], acc);
        gdst[(size_t)(row0 + t0 + t) * WW + j] = acc;
        mx = fmaxf(mx, acc);
#pragma unroll
        for (int k = 0; k < NTAP - 1; k++) win[k] = win[k + 1];
        if (t < TH / 2 - 1) win[NTAP - 1] = Bs[(t0 + t + NTAP) * WW + j];
    }
    return mx;
}

__global__ void __launch_bounds__(NT, 2) mapK(const float* __restrict__ x) {
    extern __shared__ char smem[];
    uint32_t* As = (uint32_t*)smem;
    float* Bs = (float*)(smem + AROWS * AWORDS * 4);
    __shared__ float red[16];

    const int row0 = blockIdx.x * TH;
    const int b = blockIdx.y;
    const int j = threadIdx.x & (WW - 1);
    const int rh = threadIdx.x >> 8;

    fillA(x, b, 0, row0, As);
    __syncthreads();

    for (int m = 0; m < 3; m++) {
        const float i2s = (m == 2) ? 2.0f : 0.5f;   // 1/(2*sigma^2)
        float w[RAD + 1];
#pragma unroll
        for (int d = 0; d <= RAD; d++) w[d] = __expf(-(float)(d * d) * i2s);

        convW(As, Bs, w);
        __syncthreads();

        if (m < 2) fillA(x, b, m + 1, row0, As);   // prefetch next mask (As free now)

        float mx = hconvStore(Bs, w, &g_map[m][b][0][0], row0, j, rh);

        // block max -> one atomic (all values >= 0; int compare order-preserving)
#pragma unroll
        for (int off = 16; off; off >>= 1)
            mx = fmaxf(mx, __shfl_xor_sync(0xFFFFFFFFu, mx, off));
        if ((threadIdx.x & 31) == 0) red[threadIdx.x >> 5] = mx;
        __syncthreads();
        if (threadIdx.x < 16) {
            float v = red[threadIdx.x];
#pragma unroll
            for (int off = 8; off; off >>= 1)
                v = fmaxf(v, __shfl_xor_sync(0xFFFFu, v, off));
            if (threadIdx.x == 0)
                atomicMax((int*)&g_max[m * BB + b], __float_as_int(v));
        }
        __syncthreads();   // Bs free for next convW, red free for next reduce
    }
}

// Pure-memory finalize: normalize + assemble 5 channels, float4 throughout.
__global__ void __launch_bounds__(256) finK(const float* __restrict__ x,
                                            float* __restrict__ out) {
    const int b = blockIdx.y;
    const size_t px = ((size_t)blockIdx.x << 10) | ((size_t)threadIdx.x << 2);
    const size_t plane = (size_t)HH * WW;

    float mt = g_max[b];          float st = 1.0f / ((mt == 0.f) ? 1.f : mt);
    float mc = g_max[BB + b];     float sc = 1.0f / ((mc == 0.f) ? 1.f : mc);
    float mh = g_max[2 * BB + b]; float sh = 1.0f / ((mh == 0.f) ? 1.f : mh);

    float4 t = *(const float4*)(&g_map[0][b][0][0] + px);
    float4 c = *(const float4*)(&g_map[1][b][0][0] + px);
    float4 h = *(const float4*)(&g_map[2][b][0][0] + px);
    float4 x0 = *(const float4*)(x + (size_t)b * 4 * plane + px);

    t.x *= st; t.y *= st; t.z *= st; t.w *= st;
    c.x *= sc; c.y *= sc; c.z *= sc; c.w *= sc;
    h.x *= sh; h.y *= sh; h.z *= sh; h.w *= sh;
    float4 mu = make_float4(t.x * c.x, t.y * c.y, t.z * c.z, t.w * c.w);

    float* ob = out + (size_t)b * 5 * plane;
    *(float4*)(ob + px) = x0;
    *(float4*)(ob + plane + px) = t;
    *(float4*)(ob + 2 * plane + px) = c;
    *(float4*)(ob + 3 * plane + px) = h;
    *(float4*)(ob + 4 * plane + px) = mu;
}

extern "C" void kernel_launch(void* const* d_in, const int* in_sizes, int n_in,
                              void* d_out, int out_size) {
    const float* x = (const float*)d_in[0];
    float* out = (float*)d_out;

    cudaFuncSetAttribute(mapK, cudaFuncAttributeMaxDynamicSharedMemorySize, SMEM_BYTES);

    mapK<<<dim3(HH / TH, BB), NT, SMEM_BYTES>>>(x);
    finK<<<dim3(64, BB), 256>>>(x, out);
}